// round 9
// baseline (speedup 1.0000x reference)
#include <cuda_runtime.h>
#include <cuda_bf16.h>
#include <stdint.h>
#include <math_constants.h>

// Problem constants
#define B_   2
#define S_   2048
#define D_   1024
#define H_   16
#define DH_  64
#define MTOT (B_ * S_)          // 4096
#define MASK_N (B_ * S_ * S_)   // 8388608
#define KSPLIT 3072             // K' = 3*1024 (bf16 split folded into K)
#define AELEMS (MTOT * KSPLIT)
#define WELEMS (D_ * KSPLIT)

// Scratch (device globals — allocation-free per harness rules)
__device__ int      g_mask_flags;
__device__ uint64_t g_mbits[MASK_N / 64];           // bit-packed mask
__device__ float    g_ctx[MTOT * D_];               // natural head layout [B,H,S,DH]
__device__ unsigned short g_abuf[3][AELEMS];        // split A' for q,k,v inputs
__device__ unsigned short g_actx[AELEMS];           // split A' for ctx
__device__ unsigned short g_wbuf[4][WELEMS];        // split W' for Wq,Wk,Wv,Wo
__device__ unsigned short g_qhi[MTOT * D_];         // [B,H,S,DH] bf16
__device__ unsigned short g_qlo[MTOT * D_];
__device__ unsigned short g_khi[MTOT * D_];
__device__ unsigned short g_klo[MTOT * D_];
__device__ unsigned short g_vhiT[MTOT * D_];        // [B,H,DH,S] bf16
__device__ unsigned short g_vloT[MTOT * D_];

// ---------------------------------------------------------------------------
// helpers
// ---------------------------------------------------------------------------
__device__ __forceinline__ uint32_t smem_u32(const void* p) {
    uint32_t a;
    asm("{ .reg .u64 t; cvta.to.shared.u64 t, %1; cvt.u32.u64 %0, t; }"
        : "=r"(a) : "l"(p));
    return a;
}
__device__ __forceinline__ void ldsm_x4(uint32_t& r0, uint32_t& r1,
                                        uint32_t& r2, uint32_t& r3, uint32_t addr) {
    asm volatile("ldmatrix.sync.aligned.m8n8.x4.shared.b16 {%0,%1,%2,%3}, [%4];"
                 : "=r"(r0), "=r"(r1), "=r"(r2), "=r"(r3) : "r"(addr));
}
__device__ __forceinline__ void ldsm_x2(uint32_t& r0, uint32_t& r1, uint32_t addr) {
    asm volatile("ldmatrix.sync.aligned.m8n8.x2.shared.b16 {%0,%1}, [%2];"
                 : "=r"(r0), "=r"(r1) : "r"(addr));
}
__device__ __forceinline__ void mma16816(float* c, const uint32_t* a, const uint32_t* b) {
    asm volatile(
        "mma.sync.aligned.m16n8k16.row.col.f32.bf16.bf16.f32 "
        "{%0,%1,%2,%3}, {%4,%5,%6,%7}, {%8,%9}, {%0,%1,%2,%3};"
        : "+f"(c[0]), "+f"(c[1]), "+f"(c[2]), "+f"(c[3])
        : "r"(a[0]), "r"(a[1]), "r"(a[2]), "r"(a[3]), "r"(b[0]), "r"(b[1]));
}
__device__ __forceinline__ void cpa16(uint32_t saddr, const void* g) {
    asm volatile("cp.async.ca.shared.global [%0], [%1], 16;" :: "r"(saddr), "l"(g));
}
__device__ __forceinline__ unsigned short f2bf(float x) {
    return __bfloat16_as_ushort(__float2bfloat16_rn(x));
}
__device__ __forceinline__ float bf2f(unsigned short u) {
    return __bfloat162float(__ushort_as_bfloat16(u));
}
__device__ __forceinline__ uint32_t packbf2(float a, float b) {
    return (uint32_t)f2bf(a) | ((uint32_t)f2bf(b) << 16);
}
// MUFU-free exp2: scores arrive pre-scaled by log2(e), so this is exp().
__device__ __forceinline__ float exp2_fast(float y0) {
    float y = fmaxf(y0, -126.0f);
    const float t  = y + 12582912.0f;           // round-to-nearest integer
    const float nf = t - 12582912.0f;
    const float f  = y - nf;
    float p = 0.0013339075f;
    p = fmaf(p, f, 0.0096181691f);
    p = fmaf(p, f, 0.0555041086f);
    p = fmaf(p, f, 0.2402265069f);
    p = fmaf(p, f, 0.6931471806f);
    p = fmaf(p, f, 1.0f);
    return __int_as_float(__float_as_int(p) + (((int)nf) << 23));
}

// ---------------------------------------------------------------------------
// Mask dtype detection (verified) + bit-pack conversion
// ---------------------------------------------------------------------------
__global__ __launch_bounds__(256) void detect_mask_kernel(const uint32_t* __restrict__ raw)
{
    __shared__ int sflags[256];
    int f = 0;
    const int tid = threadIdx.x;
    #pragma unroll
    for (int i = 0; i < 16; i++) {
        const uint32_t w = raw[tid * 16 + i];
        if (w != 0u && w != 1u)          f |= 1;
        if (w != 0u && w != 0x3F800000u) f |= 2;
    }
    sflags[tid] = f;
    __syncthreads();
    for (int s = 128; s > 0; s >>= 1) {
        if (tid < s) sflags[tid] |= sflags[tid + s];
        __syncthreads();
    }
    if (tid == 0) g_mask_flags = sflags[0];
}

__global__ __launch_bounds__(256) void bitpack_mask_kernel(const void* __restrict__ raw)
{
    const int flags = g_mask_flags;
    const size_t t = (size_t)blockIdx.x * 256 + threadIdx.x;   // 0..131071
    uint64_t w = 0;
    if ((flags & 1) == 0) {              // int32 0/1
        const int4* p = reinterpret_cast<const int4*>((const int*)raw + t * 64);
        #pragma unroll
        for (int i = 0; i < 16; i++) {
            const int4 v = p[i];
            w |= (uint64_t)(v.x != 0) << (i * 4 + 0);
            w |= (uint64_t)(v.y != 0) << (i * 4 + 1);
            w |= (uint64_t)(v.z != 0) << (i * 4 + 2);
            w |= (uint64_t)(v.w != 0) << (i * 4 + 3);
        }
    } else if ((flags & 2) == 0) {       // float32 0/1
        const float4* p = reinterpret_cast<const float4*>((const float*)raw + t * 64);
        #pragma unroll
        for (int i = 0; i < 16; i++) {
            const float4 v = p[i];
            w |= (uint64_t)(v.x != 0.f) << (i * 4 + 0);
            w |= (uint64_t)(v.y != 0.f) << (i * 4 + 1);
            w |= (uint64_t)(v.z != 0.f) << (i * 4 + 2);
            w |= (uint64_t)(v.w != 0.f) << (i * 4 + 3);
        }
    } else {                             // uint8 bool
        const uint4* p = reinterpret_cast<const uint4*>((const uint8_t*)raw + t * 64);
        #pragma unroll
        for (int i = 0; i < 4; i++) {
            const uint4 v = p[i];
            const uint32_t u[4] = {v.x, v.y, v.z, v.w};
            #pragma unroll
            for (int j = 0; j < 4; j++) {
                #pragma unroll
                for (int bb = 0; bb < 4; bb++) {
                    w |= (uint64_t)(((u[j] >> (bb * 8)) & 0xffu) != 0)
                         << (i * 16 + j * 4 + bb);
                }
            }
        }
    }
    g_mbits[t] = w;
}

// ---------------------------------------------------------------------------
// Split-bf16 conversion:  A' = [hi|hi|lo],  W' = [hi|lo|hi]   (K'=3072)
// ---------------------------------------------------------------------------
__global__ __launch_bounds__(256) void split_all_A_kernel(
    const float* __restrict__ A0, const float* __restrict__ A1,
    const float* __restrict__ A2)
{
    const int which = blockIdx.x >> 12;
    const int t  = (blockIdx.x & 4095) * 256 + threadIdx.x;
    const int e0 = t * 4;
    const int m  = e0 >> 10, k = e0 & 1023;
    const float* A = (which == 0) ? A0 : (which == 1) ? A1 : A2;
    const float4 v = *reinterpret_cast<const float4*>(A + (size_t)m * D_ + k);
    ushort4 hi = make_ushort4(f2bf(v.x), f2bf(v.y), f2bf(v.z), f2bf(v.w));
    ushort4 lo = make_ushort4(f2bf(v.x - bf2f(hi.x)), f2bf(v.y - bf2f(hi.y)),
                              f2bf(v.z - bf2f(hi.z)), f2bf(v.w - bf2f(hi.w)));
    unsigned short* dst = g_abuf[which];
    const size_t base = (size_t)m * KSPLIT;
    *reinterpret_cast<ushort4*>(dst + base + k)        = hi;
    *reinterpret_cast<ushort4*>(dst + base + 1024 + k) = hi;
    *reinterpret_cast<ushort4*>(dst + base + 2048 + k) = lo;
}

// ctx split: gather from [B,H,S,DH] natural head layout
__global__ __launch_bounds__(256) void split_ctx_kernel()
{
    const int t  = blockIdx.x * 256 + threadIdx.x;
    const int e0 = t * 4;
    const int m  = e0 >> 10, k = e0 & 1023;
    const int b = m >> 11, s = m & (S_ - 1);
    const int h = k >> 6, dh = k & 63;
    const float4 v = *reinterpret_cast<const float4*>(
        g_ctx + ((((size_t)b * H_ + h) * S_ + s) << 6) + dh);
    ushort4 hi = make_ushort4(f2bf(v.x), f2bf(v.y), f2bf(v.z), f2bf(v.w));
    ushort4 lo = make_ushort4(f2bf(v.x - bf2f(hi.x)), f2bf(v.y - bf2f(hi.y)),
                              f2bf(v.z - bf2f(hi.z)), f2bf(v.w - bf2f(hi.w)));
    const size_t base = (size_t)m * KSPLIT;
    *reinterpret_cast<ushort4*>(g_actx + base + k)        = hi;
    *reinterpret_cast<ushort4*>(g_actx + base + 1024 + k) = hi;
    *reinterpret_cast<ushort4*>(g_actx + base + 2048 + k) = lo;
}

__global__ __launch_bounds__(256) void split_all_W_kernel(
    const float* __restrict__ W0, const float* __restrict__ W1,
    const float* __restrict__ W2, const float* __restrict__ W3)
{
    const int which = blockIdx.x >> 10;
    const int t  = (blockIdx.x & 1023) * 256 + threadIdx.x;
    const int e0 = t * 4;
    const int n  = e0 >> 10, k = e0 & 1023;
    const float* W = (which == 0) ? W0 : (which == 1) ? W1 : (which == 2) ? W2 : W3;
    const float4 v = *reinterpret_cast<const float4*>(W + (size_t)n * D_ + k);
    ushort4 hi = make_ushort4(f2bf(v.x), f2bf(v.y), f2bf(v.z), f2bf(v.w));
    ushort4 lo = make_ushort4(f2bf(v.x - bf2f(hi.x)), f2bf(v.y - bf2f(hi.y)),
                              f2bf(v.z - bf2f(hi.z)), f2bf(v.w - bf2f(hi.w)));
    unsigned short* dst = g_wbuf[which];
    const size_t base = (size_t)n * KSPLIT;
    *reinterpret_cast<ushort4*>(dst + base + k)        = hi;
    *reinterpret_cast<ushort4*>(dst + base + 1024 + k) = lo;
    *reinterpret_cast<ushort4*>(dst + base + 2048 + k) = hi;
}

// ---------------------------------------------------------------------------
// HMMA GEMM (verified R5-R8): C[m][n] = sum_k A'[m][k]*W'[n][k] (+bias)*scale
//   omode 0: fp32 out[m][D_ cols]   (bias[n])
//   omode 3: bf16 hi/lo -> natural [B,H,S,DH]; m=token, n=feature (bias[n])
//   omode 4: bf16 hi/lo -> V^T [B,H,DH,S];    m=feature, n=token  (bias[m])
// ---------------------------------------------------------------------------
#define BK    32
#define SST   40
#define SMATE (128 * SST)
#define STAGE (2 * SMATE)
#define NCHUNK (KSPLIT / BK)         // 96

__global__ __launch_bounds__(256, 1) void mma_gemm_kernel(
    const unsigned short* __restrict__ Abuf, const unsigned short* __restrict__ Wbuf,
    const float* __restrict__ bias, float* __restrict__ out,
    unsigned short* __restrict__ ohi, unsigned short* __restrict__ olo,
    int omode, float scale)
{
    __shared__ __align__(16) unsigned short sbuf[2 * STAGE];  // 40960 B

    const int tid  = threadIdx.x;
    const int wid  = tid >> 5, lane = tid & 31;
    const int wm   = wid >> 2, wn = wid & 3;
    const int m0   = blockIdx.y * 128, n0 = blockIdx.x * 128;

    const uint32_t sb = smem_u32(sbuf);

    float acc[4][4][4];
    #pragma unroll
    for (int i = 0; i < 4; i++)
        #pragma unroll
        for (int j = 0; j < 4; j++)
            #pragma unroll
            for (int e = 0; e < 4; e++) acc[i][j][e] = 0.f;

    const int lrow0 = tid >> 2, lseg = (tid & 3) * 8;

    {
        const unsigned short* Ap = Abuf + (size_t)(m0 + lrow0) * KSPLIT + lseg;
        const unsigned short* Bp = Wbuf + (size_t)(n0 + lrow0) * KSPLIT + lseg;
        *reinterpret_cast<uint4*>(sbuf + lrow0 * SST + lseg) =
            *reinterpret_cast<const uint4*>(Ap);
        *reinterpret_cast<uint4*>(sbuf + (lrow0 + 64) * SST + lseg) =
            *reinterpret_cast<const uint4*>(Ap + (size_t)64 * KSPLIT);
        *reinterpret_cast<uint4*>(sbuf + SMATE + lrow0 * SST + lseg) =
            *reinterpret_cast<const uint4*>(Bp);
        *reinterpret_cast<uint4*>(sbuf + SMATE + (lrow0 + 64) * SST + lseg) =
            *reinterpret_cast<const uint4*>(Bp + (size_t)64 * KSPLIT);
    }
    __syncthreads();

    const int a_row  = wm * 64 + (lane & 15);
    const int a_colh = (lane >> 4) * 8;
    const int b_row  = wn * 32 + (lane & 7);
    const int b_colh = ((lane >> 3) & 1) * 8;

    for (int c = 0; c < NCHUNK; c++) {
        const int st = c & 1;
        const uint32_t sa  = sb + (uint32_t)(st * STAGE) * 2;
        const uint32_t sbm = sa + (uint32_t)SMATE * 2;

        uint4 pa0, pa1, pb0, pb1;
        if (c + 1 < NCHUNK) {
            const int k0 = (c + 1) * BK;
            const unsigned short* Ap = Abuf + (size_t)(m0 + lrow0) * KSPLIT + k0 + lseg;
            const unsigned short* Bp = Wbuf + (size_t)(n0 + lrow0) * KSPLIT + k0 + lseg;
            pa0 = *reinterpret_cast<const uint4*>(Ap);
            pa1 = *reinterpret_cast<const uint4*>(Ap + (size_t)64 * KSPLIT);
            pb0 = *reinterpret_cast<const uint4*>(Bp);
            pb1 = *reinterpret_cast<const uint4*>(Bp + (size_t)64 * KSPLIT);
        }

        #pragma unroll
        for (int ks = 0; ks < 2; ks++) {
            uint32_t a[4][4], b[4][2];
            #pragma unroll
            for (int mt = 0; mt < 4; mt++) {
                const uint32_t addr = sa +
                    ((a_row + mt * 16) * SST + ks * 16 + a_colh) * 2;
                ldsm_x4(a[mt][0], a[mt][1], a[mt][2], a[mt][3], addr);
            }
            #pragma unroll
            for (int nt = 0; nt < 4; nt++) {
                const uint32_t addr = sbm +
                    ((b_row + nt * 8) * SST + ks * 16 + b_colh) * 2;
                ldsm_x2(b[nt][0], b[nt][1], addr);
            }
            #pragma unroll
            for (int mt = 0; mt < 4; mt++)
                #pragma unroll
                for (int nt = 0; nt < 4; nt++)
                    mma16816(acc[mt][nt], a[mt], b[nt]);
        }

        if (c + 1 < NCHUNK) {
            unsigned short* d = sbuf + (st ^ 1) * STAGE;
            *reinterpret_cast<uint4*>(d + lrow0 * SST + lseg) = pa0;
            *reinterpret_cast<uint4*>(d + (lrow0 + 64) * SST + lseg) = pa1;
            *reinterpret_cast<uint4*>(d + SMATE + lrow0 * SST + lseg) = pb0;
            *reinterpret_cast<uint4*>(d + SMATE + (lrow0 + 64) * SST + lseg) = pb1;
        }
        __syncthreads();
    }

    const int gr = lane >> 2, gc = (lane & 3) * 2;
    #pragma unroll
    for (int mt = 0; mt < 4; mt++) {
        #pragma unroll
        for (int nt = 0; nt < 4; nt++) {
            const int n = n0 + wn * 32 + nt * 8 + gc;
            #pragma unroll
            for (int half = 0; half < 2; half++) {
                const int m = m0 + wm * 64 + mt * 16 + gr + half * 8;
                float bb0, bb1;
                if (omode == 4) { bb0 = bb1 = bias[m]; }
                else           { bb0 = bias[n]; bb1 = bias[n + 1]; }
                const float v0 = (acc[mt][nt][half * 2 + 0] + bb0) * scale;
                const float v1 = (acc[mt][nt][half * 2 + 1] + bb1) * scale;
                if (omode == 0) {
                    *reinterpret_cast<float2*>(out + (size_t)m * D_ + n) =
                        make_float2(v0, v1);
                } else if (omode == 3) {
                    const int bb = m >> 11, s = m & (S_ - 1);
                    const int hh = n >> 6, dh = n & 63;
                    const size_t ad = (((size_t)bb * H_ + hh) * S_ + s) * DH_ + dh;
                    const ushort2 sh = make_ushort2(f2bf(v0), f2bf(v1));
                    const ushort2 sl = make_ushort2(f2bf(v0 - bf2f(sh.x)),
                                                    f2bf(v1 - bf2f(sh.y)));
                    *reinterpret_cast<ushort2*>(ohi + ad) = sh;
                    *reinterpret_cast<ushort2*>(olo + ad) = sl;
                } else {  // omode 4: V^T
                    const int hh = m >> 6, dh = m & 63;
                    const int bb = n >> 11, s = n & (S_ - 1);
                    const size_t ad = (((size_t)bb * H_ + hh) * DH_ + dh) * S_ + s;
                    const ushort2 sh = make_ushort2(f2bf(v0), f2bf(v1));
                    const ushort2 sl = make_ushort2(f2bf(v0 - bf2f(sh.x)),
                                                    f2bf(v1 - bf2f(sh.y)));
                    *reinterpret_cast<ushort2*>(ohi + ad) = sh;
                    *reinterpret_cast<ushort2*>(olo + ad) = sl;
                }
            }
        }
    }
}

// ---------------------------------------------------------------------------
// Tensorized flash attention (R6 structure exactly): Q frags in registers,
// 1 CTA/SM, cp.async double-buffer, bit-packed mask, fp32 coalesced ctx out.
// Scores are in log2 domain (Q pre-scaled by 0.125*log2(e)).
// ---------------------------------------------------------------------------
#define FST   72                     // smem row stride (ushort), conflict-free
#define FARRB (64 * FST * 2)         // bytes per 64-row array = 9216
#define FSTGB (4 * FARRB)            // per KV stage = 36864 B
#define FSMEM (2 * FSTGB)            // 73728 B

__global__ __launch_bounds__(256, 1) void flash_mma_kernel()
{
    extern __shared__ __align__(16) unsigned char fsm[];
    const int tid = threadIdx.x, w = tid >> 5, lane = tid & 31;
    const int q0 = blockIdx.x * 128;
    const int h  = blockIdx.y, b = blockIdx.z;
    const size_t hb = ((size_t)b * H_ + h) * (size_t)(S_ * DH_);
    const uint32_t sb = smem_u32(fsm);

    // ---- Q staged through smem (hi at 0, lo at FSTGB), frags -> registers
    #pragma unroll
    for (int i = 0; i < 4; i++) {
        const int f = tid + i * 256;
        const int r = f >> 3, sg = f & 7;
        const size_t gq = hb + (size_t)(q0 + r) * DH_ + sg * 8;
        *reinterpret_cast<uint4*>(fsm + (r * FST + sg * 8) * 2) =
            *reinterpret_cast<const uint4*>(g_qhi + gq);
        *reinterpret_cast<uint4*>(fsm + FSTGB + (r * FST + sg * 8) * 2) =
            *reinterpret_cast<const uint4*>(g_qlo + gq);
    }
    __syncthreads();
    uint32_t qh[4][4], ql[4][4];
    {
        const int ar = w * 16 + (lane & 15);
        const int ac = (lane >> 4) * 8;
        #pragma unroll
        for (int kc = 0; kc < 4; kc++) {
            const uint32_t ad = sb + (ar * FST + kc * 16 + ac) * 2;
            ldsm_x4(qh[kc][0], qh[kc][1], qh[kc][2], qh[kc][3], ad);
            ldsm_x4(ql[kc][0], ql[kc][1], ql[kc][2], ql[kc][3], ad + FSTGB);
        }
    }
    __syncthreads();

    const int gr = lane >> 2, gc = (lane & 3) * 2;
    const int brow  = (lane & 7) + ((lane >> 4) & 1) * 8;
    const int bcolh = ((lane >> 3) & 1) * 8;

    float o_[8][4];
    #pragma unroll
    for (int nt = 0; nt < 8; nt++)
        #pragma unroll
        for (int e = 0; e < 4; e++) o_[nt][e] = 0.f;
    float mI[2] = {-1e30f, -1e30f}, lI[2] = {0.f, 0.f};

    auto issue_kv = [&](int kt, int st) {
        const uint32_t s0 = sb + st * FSTGB;
        const int k0 = kt * 64;
        #pragma unroll
        for (int i = 0; i < 2; i++) {
            const int f = tid + i * 256;
            const int r = f >> 3, sg = f & 7;
            const uint32_t so = (r * FST + sg * 8) * 2;
            const size_t kg = hb + (size_t)(k0 + r) * DH_ + sg * 8;
            cpa16(s0 + so,             g_khi + kg);
            cpa16(s0 + FARRB + so,     g_klo + kg);
            const size_t vg = hb + (size_t)r * S_ + k0 + sg * 8;
            cpa16(s0 + 2 * FARRB + so, g_vhiT + vg);
            cpa16(s0 + 3 * FARRB + so, g_vloT + vg);
        }
    };

    issue_kv(0, 0);
    asm volatile("cp.async.commit_group;" ::: "memory");

    for (int kt = 0; kt < S_ / 64; kt++) {
        const int st = kt & 1;
        if (kt + 1 < S_ / 64) {
            issue_kv(kt + 1, st ^ 1);
            asm volatile("cp.async.commit_group;" ::: "memory");
            asm volatile("cp.async.wait_group 1;" ::: "memory");
        } else {
            asm volatile("cp.async.wait_group 0;" ::: "memory");
        }
        __syncthreads();

        const uint32_t sk = sb + st * FSTGB;

        // ---- QK^T: 3-term split
        float s_[8][4];
        #pragma unroll
        for (int nt = 0; nt < 8; nt++)
            #pragma unroll
            for (int e = 0; e < 4; e++) s_[nt][e] = 0.f;

        #pragma unroll
        for (int kc = 0; kc < 4; kc++) {
            #pragma unroll
            for (int ntp = 0; ntp < 4; ntp++) {
                const uint32_t ad = sk + ((ntp * 16 + brow) * FST + kc * 16 + bcolh) * 2;
                uint32_t r0, r1, r2, r3;
                ldsm_x4(r0, r1, r2, r3, ad);
                { uint32_t b0[2] = {r0, r1}, b1[2] = {r2, r3};
                  mma16816(s_[2 * ntp],     qh[kc], b0);
                  mma16816(s_[2 * ntp + 1], qh[kc], b1);
                  mma16816(s_[2 * ntp],     ql[kc], b0);
                  mma16816(s_[2 * ntp + 1], ql[kc], b1); }
                ldsm_x4(r0, r1, r2, r3, ad + FARRB);
                { uint32_t b0[2] = {r0, r1}, b1[2] = {r2, r3};
                  mma16816(s_[2 * ntp],     qh[kc], b0);
                  mma16816(s_[2 * ntp + 1], qh[kc], b1); }
            }
        }

        // ---- mask via bit words (1 uint64 per row per tile)
        #pragma unroll
        for (int rh = 0; rh < 2; rh++) {
            const int row = q0 + w * 16 + gr + rh * 8;
            const uint64_t mw = g_mbits[((size_t)b * S_ + row) * (S_ / 64) + kt];
            #pragma unroll
            for (int nt = 0; nt < 8; nt++) {
                const int j = nt * 8 + gc;
                if ((mw >> j) & 1ull)       s_[nt][rh * 2 + 0] = -1e30f;
                if ((mw >> (j + 1)) & 1ull) s_[nt][rh * 2 + 1] = -1e30f;
            }
        }

        // ---- online softmax in exp2 domain (row = 4 lanes of a quad)
        float alpha[2];
        #pragma unroll
        for (int rh = 0; rh < 2; rh++) {
            float rmax = -1e30f;
            #pragma unroll
            for (int nt = 0; nt < 8; nt++)
                rmax = fmaxf(rmax, fmaxf(s_[nt][rh * 2], s_[nt][rh * 2 + 1]));
            rmax = fmaxf(rmax, __shfl_xor_sync(0xffffffffu, rmax, 1));
            rmax = fmaxf(rmax, __shfl_xor_sync(0xffffffffu, rmax, 2));
            const float mn = fmaxf(mI[rh], rmax);
            alpha[rh] = exp2_fast(mI[rh] - mn);
            mI[rh] = mn;
            float rs = 0.f;
            #pragma unroll
            for (int nt = 0; nt < 8; nt++) {
                const float e0 = exp2_fast(s_[nt][rh * 2] - mn);
                const float e1 = exp2_fast(s_[nt][rh * 2 + 1] - mn);
                s_[nt][rh * 2] = e0; s_[nt][rh * 2 + 1] = e1;
                rs += e0 + e1;
            }
            rs += __shfl_xor_sync(0xffffffffu, rs, 1);
            rs += __shfl_xor_sync(0xffffffffu, rs, 2);
            lI[rh] = lI[rh] * alpha[rh] + rs;
        }
        #pragma unroll
        for (int nt = 0; nt < 8; nt++)
            #pragma unroll
            for (int e = 0; e < 4; e++) o_[nt][e] *= alpha[e >> 1];

        // ---- P @ V: 3-term split (P frags from score C-frags)
        const uint32_t sv = sk + 2 * FARRB;
        #pragma unroll
        for (int kc2 = 0; kc2 < 4; kc2++) {
            uint32_t ah[4], al[4];
            #pragma unroll
            for (int jj = 0; jj < 2; jj++) {
                const float* sp = s_[2 * kc2 + jj];
                const unsigned short h0 = f2bf(sp[0]), h1 = f2bf(sp[1]);
                const unsigned short h2 = f2bf(sp[2]), h3 = f2bf(sp[3]);
                ah[jj * 2 + 0] = (uint32_t)h0 | ((uint32_t)h1 << 16);
                ah[jj * 2 + 1] = (uint32_t)h2 | ((uint32_t)h3 << 16);
                al[jj * 2 + 0] = packbf2(sp[0] - bf2f(h0), sp[1] - bf2f(h1));
                al[jj * 2 + 1] = packbf2(sp[2] - bf2f(h2), sp[3] - bf2f(h3));
            }
            #pragma unroll
            for (int ntp = 0; ntp < 4; ntp++) {
                const uint32_t ad = sv + ((ntp * 16 + brow) * FST + kc2 * 16 + bcolh) * 2;
                uint32_t r0, r1, r2, r3;
                ldsm_x4(r0, r1, r2, r3, ad);
                { uint32_t b0[2] = {r0, r1}, b1[2] = {r2, r3};
                  mma16816(o_[2 * ntp],     ah, b0);
                  mma16816(o_[2 * ntp + 1], ah, b1);
                  mma16816(o_[2 * ntp],     al, b0);
                  mma16816(o_[2 * ntp + 1], al, b1); }
                ldsm_x4(r0, r1, r2, r3, ad + FARRB);
                { uint32_t b0[2] = {r0, r1}, b1[2] = {r2, r3};
                  mma16816(o_[2 * ntp],     ah, b0);
                  mma16816(o_[2 * ntp + 1], ah, b1); }
            }
        }
        __syncthreads();
    }

    // ---- finalize: coalesced fp32 ctx, natural head layout [B,H,S,DH]
    const float inv0 = 1.f / lI[0], inv1 = 1.f / lI[1];
    #pragma unroll
    for (int nt = 0; nt < 8; nt++) {
        const int d = nt * 8 + gc;
        const int qA = q0 + w * 16 + gr;
        *reinterpret_cast<float2*>(g_ctx + hb + (size_t)qA * DH_ + d) =
            make_float2(o_[nt][0] * inv0, o_[nt][1] * inv0);
        *reinterpret_cast<float2*>(g_ctx + hb + (size_t)(qA + 8) * DH_ + d) =
            make_float2(o_[nt][2] * inv1, o_[nt][3] * inv1);
    }
}

// ---------------------------------------------------------------------------
extern "C" void kernel_launch(void* const* d_in, const int* in_sizes, int n_in,
                              void* d_out, int out_size)
{
    const float* key   = (const float*)d_in[0];
    const float* value = (const float*)d_in[1];
    const float* query = (const float*)d_in[2];
    const void*  mask  = d_in[3];
    const float* Wq = (const float*)d_in[4];
    const float* bq = (const float*)d_in[5];
    const float* Wk = (const float*)d_in[6];
    const float* bk = (const float*)d_in[7];
    const float* Wv = (const float*)d_in[8];
    const float* bv = (const float*)d_in[9];
    const float* Wo = (const float*)d_in[10];
    const float* bo = (const float*)d_in[11];
    float* out = (float*)d_out;

    void *pab, *pcx, *pwb, *pqh, *pql, *pkh, *pkl, *pvh, *pvl;
    cudaGetSymbolAddress(&pab, g_abuf);
    cudaGetSymbolAddress(&pcx, g_actx);
    cudaGetSymbolAddress(&pwb, g_wbuf);
    cudaGetSymbolAddress(&pqh, g_qhi);
    cudaGetSymbolAddress(&pql, g_qlo);
    cudaGetSymbolAddress(&pkh, g_khi);
    cudaGetSymbolAddress(&pkl, g_klo);
    cudaGetSymbolAddress(&pvh, g_vhiT);
    cudaGetSymbolAddress(&pvl, g_vloT);
    unsigned short* ab = (unsigned short*)pab;
    unsigned short* wb = (unsigned short*)pwb;

    // mask normalization (dtype-agnostic) -> bit words
    detect_mask_kernel<<<1, 256>>>((const uint32_t*)mask);
    bitpack_mask_kernel<<<(MASK_N / 64) / 256, 256>>>(mask);

    // all input splits up front
    split_all_A_kernel<<<3 * 4096, 256>>>(query, key, value);
    split_all_W_kernel<<<4 * 1024, 256>>>(Wq, Wk, Wv, Wo);

    const dim3 gg(D_ / 128, MTOT / 128);    // (8, 32): m = tokens
    const dim3 gv(MTOT / 128, D_ / 128);    // (32, 8): m = features (V^T)

    // Q -> bf16 hi/lo natural, pre-scaled by (1/sqrt(DH)) * log2(e)  (exp2 domain)
    mma_gemm_kernel<<<gg, 256>>>(ab + 0 * (size_t)AELEMS, wb + 0 * (size_t)WELEMS,
                                 bq, nullptr,
                                 (unsigned short*)pqh, (unsigned short*)pql,
                                 3, 0.125f * 1.4426950408889634f);
    // K -> bf16 hi/lo natural
    mma_gemm_kernel<<<gg, 256>>>(ab + 1 * (size_t)AELEMS, wb + 1 * (size_t)WELEMS,
                                 bk, nullptr,
                                 (unsigned short*)pkh, (unsigned short*)pkl, 3, 1.f);
    // V -> bf16 hi/lo transposed [B,H,DH,S] via swapped operands
    mma_gemm_kernel<<<gv, 256>>>(wb + 2 * (size_t)WELEMS, ab + 2 * (size_t)AELEMS,
                                 bv, nullptr,
                                 (unsigned short*)pvh, (unsigned short*)pvl, 4, 1.f);

    // attention (tensorized, R6 config) -> fp32 ctx (coalesced)
    cudaFuncSetAttribute(flash_mma_kernel,
                         cudaFuncAttributeMaxDynamicSharedMemorySize, FSMEM);
    flash_mma_kernel<<<dim3(S_ / 128, H_, B_), 256, FSMEM>>>();

    // ctx -> split-bf16 (coalesced), then output projection
    split_ctx_kernel<<<4096, 256>>>();
    mma_gemm_kernel<<<gg, 256>>>((const unsigned short*)pcx, wb + 3 * (size_t)WELEMS,
                                 bo, out, nullptr, nullptr, 0, 1.f);
}

// round 12
// speedup vs baseline: 1.1161x; 1.1161x over previous
#include <cuda_runtime.h>
#include <cuda_bf16.h>
#include <stdint.h>
#include <math_constants.h>

// Problem constants
#define B_   2
#define S_   2048
#define D_   1024
#define H_   16
#define DH_  64
#define MTOT (B_ * S_)          // 4096
#define MASK_N (B_ * S_ * S_)   // 8388608
#define KSPLIT 3072             // K' = 3*1024 (bf16 split folded into K)

// Scratch (device globals — allocation-free per harness rules)
__device__ int      g_mask_flags;
__device__ uint8_t  g_mask[MASK_N];
__device__ unsigned short g_abuf[MTOT * KSPLIT];  // A' bf16 [4096, 3072]
__device__ unsigned short g_wbuf[D_ * KSPLIT];    // W' bf16 [1024, 3072]
__device__ float    g_ctx[MTOT * D_];             // natural head layout [B,H,S,DH]
__device__ unsigned short g_qhi[MTOT * D_];       // [B,H,S,DH] bf16
__device__ unsigned short g_qlo[MTOT * D_];
__device__ unsigned short g_khi[MTOT * D_];
__device__ unsigned short g_klo[MTOT * D_];
__device__ unsigned short g_vhiT[MTOT * D_];      // [B,H,DH,S] bf16
__device__ unsigned short g_vloT[MTOT * D_];

// ---------------------------------------------------------------------------
// helpers
// ---------------------------------------------------------------------------
__device__ __forceinline__ uint32_t smem_u32(const void* p) {
    uint32_t a;
    asm("{ .reg .u64 t; cvta.to.shared.u64 t, %1; cvt.u32.u64 %0, t; }"
        : "=r"(a) : "l"(p));
    return a;
}
__device__ __forceinline__ void ldsm_x4(uint32_t& r0, uint32_t& r1,
                                        uint32_t& r2, uint32_t& r3, uint32_t addr) {
    asm volatile("ldmatrix.sync.aligned.m8n8.x4.shared.b16 {%0,%1,%2,%3}, [%4];"
                 : "=r"(r0), "=r"(r1), "=r"(r2), "=r"(r3) : "r"(addr));
}
__device__ __forceinline__ void ldsm_x2(uint32_t& r0, uint32_t& r1, uint32_t addr) {
    asm volatile("ldmatrix.sync.aligned.m8n8.x2.shared.b16 {%0,%1}, [%2];"
                 : "=r"(r0), "=r"(r1) : "r"(addr));
}
__device__ __forceinline__ void mma16816(float* c, const uint32_t* a, const uint32_t* b) {
    asm volatile(
        "mma.sync.aligned.m16n8k16.row.col.f32.bf16.bf16.f32 "
        "{%0,%1,%2,%3}, {%4,%5,%6,%7}, {%8,%9}, {%0,%1,%2,%3};"
        : "+f"(c[0]), "+f"(c[1]), "+f"(c[2]), "+f"(c[3])
        : "r"(a[0]), "r"(a[1]), "r"(a[2]), "r"(a[3]), "r"(b[0]), "r"(b[1]));
}
__device__ __forceinline__ void cpa16(uint32_t saddr, const void* g) {
    asm volatile("cp.async.ca.shared.global [%0], [%1], 16;" :: "r"(saddr), "l"(g));
}
__device__ __forceinline__ unsigned short f2bf(float x) {
    return __bfloat16_as_ushort(__float2bfloat16_rn(x));
}
__device__ __forceinline__ float bf2f(unsigned short u) {
    return __bfloat162float(__ushort_as_bfloat16(u));
}
__device__ __forceinline__ uint32_t packbf2(float a, float b) {
    return (uint32_t)f2bf(a) | ((uint32_t)f2bf(b) << 16);
}
// MUFU-free exp: magic round + deg-5 exp2 poly + exponent add. x <= 0 expected.
__device__ __forceinline__ float exp_fast(float x) {
    float y = fmaxf(x * 1.4426950408889634f, -126.0f);
    const float t  = y + 12582912.0f;
    const float nf = t - 12582912.0f;
    const float f  = y - nf;
    float p = 0.0013339075f;
    p = fmaf(p, f, 0.0096181691f);
    p = fmaf(p, f, 0.0555041086f);
    p = fmaf(p, f, 0.2402265069f);
    p = fmaf(p, f, 0.6931471806f);
    p = fmaf(p, f, 1.0f);
    return __int_as_float(__float_as_int(p) + (((int)nf) << 23));
}

// ---------------------------------------------------------------------------
// Mask dtype detection + normalization (R2-verified, R6 form)
// ---------------------------------------------------------------------------
__global__ __launch_bounds__(256) void detect_mask_kernel(const uint32_t* __restrict__ raw)
{
    __shared__ int sflags[256];
    int f = 0;
    const int tid = threadIdx.x;
    #pragma unroll
    for (int i = 0; i < 16; i++) {
        const uint32_t w = raw[tid * 16 + i];
        if (w != 0u && w != 1u)          f |= 1;
        if (w != 0u && w != 0x3F800000u) f |= 2;
    }
    sflags[tid] = f;
    __syncthreads();
    for (int s = 128; s > 0; s >>= 1) {
        if (tid < s) sflags[tid] |= sflags[tid + s];
        __syncthreads();
    }
    if (tid == 0) g_mask_flags = sflags[0];
}

__global__ __launch_bounds__(256) void convert_mask_kernel(const void* __restrict__ raw)
{
    const int flags = g_mask_flags;
    const size_t i0 = ((size_t)blockIdx.x * 256 + threadIdx.x) * 4;
    if (i0 >= MASK_N) return;
    uchar4 o;
    if ((flags & 1) == 0) {
        const int4 v = *reinterpret_cast<const int4*>((const int*)raw + i0);
        o = make_uchar4(v.x != 0, v.y != 0, v.z != 0, v.w != 0);
    } else if ((flags & 2) == 0) {
        const float4 v = *reinterpret_cast<const float4*>((const float*)raw + i0);
        o = make_uchar4(v.x != 0.f, v.y != 0.f, v.z != 0.f, v.w != 0.f);
    } else {
        o = *reinterpret_cast<const uchar4*>((const uint8_t*)raw + i0);
        o = make_uchar4(o.x != 0, o.y != 0, o.z != 0, o.w != 0);
    }
    *reinterpret_cast<uchar4*>(g_mask + i0) = o;
}

// ---------------------------------------------------------------------------
// Split-bf16 conversion:  A' = [hi|hi|lo],  W' = [hi|lo|hi]   (K'=3072)
// ---------------------------------------------------------------------------
__global__ __launch_bounds__(256) void split_A_kernel(const float* __restrict__ A, int gather)
{
    const int t  = blockIdx.x * 256 + threadIdx.x;
    const int e0 = t * 4;
    const int m  = e0 >> 10, k = e0 & 1023;
    float4 v;
    if (!gather) {
        v = *reinterpret_cast<const float4*>(A + (size_t)m * D_ + k);
    } else {
        const int b = m >> 11, s = m & (S_ - 1);
        const int h = k >> 6, dh = k & 63;
        v = *reinterpret_cast<const float4*>(
            A + ((((size_t)b * H_ + h) * S_ + s) << 6) + dh);
    }
    ushort4 hi = make_ushort4(f2bf(v.x), f2bf(v.y), f2bf(v.z), f2bf(v.w));
    ushort4 lo = make_ushort4(f2bf(v.x - bf2f(hi.x)), f2bf(v.y - bf2f(hi.y)),
                              f2bf(v.z - bf2f(hi.z)), f2bf(v.w - bf2f(hi.w)));
    const size_t base = (size_t)m * KSPLIT;
    *reinterpret_cast<ushort4*>(g_abuf + base + k)        = hi;
    *reinterpret_cast<ushort4*>(g_abuf + base + 1024 + k) = hi;
    *reinterpret_cast<ushort4*>(g_abuf + base + 2048 + k) = lo;
}

__global__ __launch_bounds__(256) void split_W_kernel(const float* __restrict__ W)
{
    const int t  = blockIdx.x * 256 + threadIdx.x;
    const int e0 = t * 4;
    const int n  = e0 >> 10, k = e0 & 1023;
    const float4 v = *reinterpret_cast<const float4*>(W + (size_t)n * D_ + k);
    ushort4 hi = make_ushort4(f2bf(v.x), f2bf(v.y), f2bf(v.z), f2bf(v.w));
    ushort4 lo = make_ushort4(f2bf(v.x - bf2f(hi.x)), f2bf(v.y - bf2f(hi.y)),
                              f2bf(v.z - bf2f(hi.z)), f2bf(v.w - bf2f(hi.w)));
    const size_t base = (size_t)n * KSPLIT;
    *reinterpret_cast<ushort4*>(g_wbuf + base + k)        = hi;
    *reinterpret_cast<ushort4*>(g_wbuf + base + 1024 + k) = lo;
    *reinterpret_cast<ushort4*>(g_wbuf + base + 2048 + k) = hi;
}

// ---------------------------------------------------------------------------
// HMMA GEMM: C[m][n] = sum_k A'[m][k]*W'[n][k] (+bias)*scale
// CTA 128x128, 8 warps (2m x 4n), warp tile 64x32, BK=32, double-buffered.
// R10 change: __launch_bounds__(256, 2) — 2 CTAs/SM (one-wave grid, latency hiding).
//   omode 0: fp32 out[m][D_ cols]   (bias[n])
//   omode 3: bf16 hi/lo -> natural [B,H,S,DH]; m=token, n=feature (bias[n])
//   omode 4: bf16 hi/lo -> V^T [B,H,DH,S];    m=feature, n=token  (bias[m])
// ---------------------------------------------------------------------------
#define BK    32
#define SST   40
#define SMATE (128 * SST)
#define STAGE (2 * SMATE)
#define NCHUNK (KSPLIT / BK)         // 96

__global__ __launch_bounds__(256, 2) void mma_gemm_kernel(
    const unsigned short* __restrict__ Abuf, const unsigned short* __restrict__ Wbuf,
    const float* __restrict__ bias, float* __restrict__ out,
    unsigned short* __restrict__ ohi, unsigned short* __restrict__ olo,
    int omode, float scale)
{
    __shared__ __align__(16) unsigned short sbuf[2 * STAGE];  // 40960 B

    const int tid  = threadIdx.x;
    const int wid  = tid >> 5, lane = tid & 31;
    const int wm   = wid >> 2, wn = wid & 3;
    const int m0   = blockIdx.y * 128, n0 = blockIdx.x * 128;

    const uint32_t sb = smem_u32(sbuf);

    float acc[4][4][4];
    #pragma unroll
    for (int i = 0; i < 4; i++)
        #pragma unroll
        for (int j = 0; j < 4; j++)
            #pragma unroll
            for (int e = 0; e < 4; e++) acc[i][j][e] = 0.f;

    const int lrow0 = tid >> 2, lseg = (tid & 3) * 8;

    {
        const unsigned short* Ap = Abuf + (size_t)(m0 + lrow0) * KSPLIT + lseg;
        const unsigned short* Bp = Wbuf + (size_t)(n0 + lrow0) * KSPLIT + lseg;
        *reinterpret_cast<uint4*>(sbuf + lrow0 * SST + lseg) =
            *reinterpret_cast<const uint4*>(Ap);
        *reinterpret_cast<uint4*>(sbuf + (lrow0 + 64) * SST + lseg) =
            *reinterpret_cast<const uint4*>(Ap + (size_t)64 * KSPLIT);
        *reinterpret_cast<uint4*>(sbuf + SMATE + lrow0 * SST + lseg) =
            *reinterpret_cast<const uint4*>(Bp);
        *reinterpret_cast<uint4*>(sbuf + SMATE + (lrow0 + 64) * SST + lseg) =
            *reinterpret_cast<const uint4*>(Bp + (size_t)64 * KSPLIT);
    }
    __syncthreads();

    const int a_row  = wm * 64 + (lane & 15);
    const int a_colh = (lane >> 4) * 8;
    const int b_row  = wn * 32 + (lane & 7);
    const int b_colh = ((lane >> 3) & 1) * 8;

    for (int c = 0; c < NCHUNK; c++) {
        const int st = c & 1;
        const uint32_t sa  = sb + (uint32_t)(st * STAGE) * 2;
        const uint32_t sbm = sa + (uint32_t)SMATE * 2;

        uint4 pa0, pa1, pb0, pb1;
        if (c + 1 < NCHUNK) {
            const int k0 = (c + 1) * BK;
            const unsigned short* Ap = Abuf + (size_t)(m0 + lrow0) * KSPLIT + k0 + lseg;
            const unsigned short* Bp = Wbuf + (size_t)(n0 + lrow0) * KSPLIT + k0 + lseg;
            pa0 = *reinterpret_cast<const uint4*>(Ap);
            pa1 = *reinterpret_cast<const uint4*>(Ap + (size_t)64 * KSPLIT);
            pb0 = *reinterpret_cast<const uint4*>(Bp);
            pb1 = *reinterpret_cast<const uint4*>(Bp + (size_t)64 * KSPLIT);
        }

        #pragma unroll
        for (int ks = 0; ks < 2; ks++) {
            uint32_t a[4][4], b[4][2];
            #pragma unroll
            for (int mt = 0; mt < 4; mt++) {
                const uint32_t addr = sa +
                    ((a_row + mt * 16) * SST + ks * 16 + a_colh) * 2;
                ldsm_x4(a[mt][0], a[mt][1], a[mt][2], a[mt][3], addr);
            }
            #pragma unroll
            for (int nt = 0; nt < 4; nt++) {
                const uint32_t addr = sbm +
                    ((b_row + nt * 8) * SST + ks * 16 + b_colh) * 2;
                ldsm_x2(b[nt][0], b[nt][1], addr);
            }
            #pragma unroll
            for (int mt = 0; mt < 4; mt++)
                #pragma unroll
                for (int nt = 0; nt < 4; nt++)
                    mma16816(acc[mt][nt], a[mt], b[nt]);
        }

        if (c + 1 < NCHUNK) {
            unsigned short* d = sbuf + (st ^ 1) * STAGE;
            *reinterpret_cast<uint4*>(d + lrow0 * SST + lseg) = pa0;
            *reinterpret_cast<uint4*>(d + (lrow0 + 64) * SST + lseg) = pa1;
            *reinterpret_cast<uint4*>(d + SMATE + lrow0 * SST + lseg) = pb0;
            *reinterpret_cast<uint4*>(d + SMATE + (lrow0 + 64) * SST + lseg) = pb1;
        }
        __syncthreads();
    }

    const int gr = lane >> 2, gc = (lane & 3) * 2;
    #pragma unroll
    for (int mt = 0; mt < 4; mt++) {
        #pragma unroll
        for (int nt = 0; nt < 4; nt++) {
            const int n = n0 + wn * 32 + nt * 8 + gc;
            #pragma unroll
            for (int half = 0; half < 2; half++) {
                const int m = m0 + wm * 64 + mt * 16 + gr + half * 8;
                float bb0, bb1;
                if (omode == 4) { bb0 = bb1 = bias[m]; }
                else           { bb0 = bias[n]; bb1 = bias[n + 1]; }
                const float v0 = (acc[mt][nt][half * 2 + 0] + bb0) * scale;
                const float v1 = (acc[mt][nt][half * 2 + 1] + bb1) * scale;
                if (omode == 0) {
                    *reinterpret_cast<float2*>(out + (size_t)m * D_ + n) =
                        make_float2(v0, v1);
                } else if (omode == 3) {
                    const int bb = m >> 11, s = m & (S_ - 1);
                    const int hh = n >> 6, dh = n & 63;
                    const size_t ad = (((size_t)bb * H_ + hh) * S_ + s) * DH_ + dh;
                    const ushort2 sh = make_ushort2(f2bf(v0), f2bf(v1));
                    const ushort2 sl = make_ushort2(f2bf(v0 - bf2f(sh.x)),
                                                    f2bf(v1 - bf2f(sh.y)));
                    *reinterpret_cast<ushort2*>(ohi + ad) = sh;
                    *reinterpret_cast<ushort2*>(olo + ad) = sl;
                } else {  // omode 4: V^T
                    const int hh = m >> 6, dh = m & 63;
                    const int bb = n >> 11, s = n & (S_ - 1);
                    const size_t ad = (((size_t)bb * H_ + hh) * DH_ + dh) * S_ + s;
                    const ushort2 sh = make_ushort2(f2bf(v0), f2bf(v1));
                    const ushort2 sl = make_ushort2(f2bf(v0 - bf2f(sh.x)),
                                                    f2bf(v1 - bf2f(sh.y)));
                    *reinterpret_cast<ushort2*>(ohi + ad) = sh;
                    *reinterpret_cast<ushort2*>(olo + ad) = sl;
                }
            }
        }
    }
}

// ---------------------------------------------------------------------------
// Tensorized flash attention (R6 verbatim): Q frags in registers, 1 CTA/SM,
// cp.async double-buffer, uchar mask, fp32 coalesced ctx out.
// ---------------------------------------------------------------------------
#define FST   72                     // smem row stride (ushort), conflict-free
#define FARRB (64 * FST * 2)         // bytes per 64-row array = 9216
#define FSTGB (4 * FARRB)            // per stage = 36864 B
#define FSMEM (2 * FSTGB)            // 73728 B

__global__ __launch_bounds__(256, 1) void flash_mma_kernel()
{
    extern __shared__ __align__(16) unsigned char fsm[];
    const int tid = threadIdx.x, w = tid >> 5, lane = tid & 31;
    const int q0 = blockIdx.x * 128;
    const int h  = blockIdx.y, b = blockIdx.z;
    const size_t hb = ((size_t)b * H_ + h) * (size_t)(S_ * DH_);
    const uint32_t sb = smem_u32(fsm);

    // ---- Q staged through smem (hi at 0, lo at FSTGB), frags -> registers
    #pragma unroll
    for (int i = 0; i < 4; i++) {
        const int f = tid + i * 256;
        const int r = f >> 3, sg = f & 7;
        const size_t gq = hb + (size_t)(q0 + r) * DH_ + sg * 8;
        *reinterpret_cast<uint4*>(fsm + (r * FST + sg * 8) * 2) =
            *reinterpret_cast<const uint4*>(g_qhi + gq);
        *reinterpret_cast<uint4*>(fsm + FSTGB + (r * FST + sg * 8) * 2) =
            *reinterpret_cast<const uint4*>(g_qlo + gq);
    }
    __syncthreads();
    uint32_t qh[4][4], ql[4][4];
    {
        const int ar = w * 16 + (lane & 15);
        const int ac = (lane >> 4) * 8;
        #pragma unroll
        for (int kc = 0; kc < 4; kc++) {
            const uint32_t ad = sb + (ar * FST + kc * 16 + ac) * 2;
            ldsm_x4(qh[kc][0], qh[kc][1], qh[kc][2], qh[kc][3], ad);
            ldsm_x4(ql[kc][0], ql[kc][1], ql[kc][2], ql[kc][3], ad + FSTGB);
        }
    }
    __syncthreads();

    const int gr = lane >> 2, gc = (lane & 3) * 2;
    const int brow  = (lane & 7) + ((lane >> 4) & 1) * 8;
    const int bcolh = ((lane >> 3) & 1) * 8;

    float o_[8][4];
    #pragma unroll
    for (int nt = 0; nt < 8; nt++)
        #pragma unroll
        for (int e = 0; e < 4; e++) o_[nt][e] = 0.f;
    float mI[2] = {-1e30f, -1e30f}, lI[2] = {0.f, 0.f};

    auto issue_kv = [&](int kt, int st) {
        const uint32_t s0 = sb + st * FSTGB;
        const int k0 = kt * 64;
        #pragma unroll
        for (int i = 0; i < 2; i++) {
            const int f = tid + i * 256;
            const int r = f >> 3, sg = f & 7;
            const uint32_t so = (r * FST + sg * 8) * 2;
            const size_t kg = hb + (size_t)(k0 + r) * DH_ + sg * 8;
            cpa16(s0 + so,             g_khi + kg);
            cpa16(s0 + FARRB + so,     g_klo + kg);
            const size_t vg = hb + (size_t)r * S_ + k0 + sg * 8;
            cpa16(s0 + 2 * FARRB + so, g_vhiT + vg);
            cpa16(s0 + 3 * FARRB + so, g_vloT + vg);
        }
    };

    issue_kv(0, 0);
    asm volatile("cp.async.commit_group;" ::: "memory");

    for (int kt = 0; kt < S_ / 64; kt++) {
        const int st = kt & 1;
        if (kt + 1 < S_ / 64) {
            issue_kv(kt + 1, st ^ 1);
            asm volatile("cp.async.commit_group;" ::: "memory");
            asm volatile("cp.async.wait_group 1;" ::: "memory");
        } else {
            asm volatile("cp.async.wait_group 0;" ::: "memory");
        }
        __syncthreads();

        const uint32_t sk = sb + st * FSTGB;

        // ---- QK^T: 3-term split
        float s_[8][4];
        #pragma unroll
        for (int nt = 0; nt < 8; nt++)
            #pragma unroll
            for (int e = 0; e < 4; e++) s_[nt][e] = 0.f;

        #pragma unroll
        for (int kc = 0; kc < 4; kc++) {
            #pragma unroll
            for (int ntp = 0; ntp < 4; ntp++) {
                const uint32_t ad = sk + ((ntp * 16 + brow) * FST + kc * 16 + bcolh) * 2;
                uint32_t r0, r1, r2, r3;
                ldsm_x4(r0, r1, r2, r3, ad);
                { uint32_t b0[2] = {r0, r1}, b1[2] = {r2, r3};
                  mma16816(s_[2 * ntp],     qh[kc], b0);
                  mma16816(s_[2 * ntp + 1], qh[kc], b1);
                  mma16816(s_[2 * ntp],     ql[kc], b0);
                  mma16816(s_[2 * ntp + 1], ql[kc], b1); }
                ldsm_x4(r0, r1, r2, r3, ad + FARRB);
                { uint32_t b0[2] = {r0, r1}, b1[2] = {r2, r3};
                  mma16816(s_[2 * ntp],     qh[kc], b0);
                  mma16816(s_[2 * ntp + 1], qh[kc], b1); }
            }
        }

        // ---- mask (canonical uint8)
        const int k0 = kt * 64;
        #pragma unroll
        for (int rh = 0; rh < 2; rh++) {
            const size_t mr = ((size_t)b * S_ + (q0 + w * 16 + gr + rh * 8)) * S_ + k0 + gc;
            #pragma unroll
            for (int nt = 0; nt < 8; nt++) {
                const uchar2 mv = *reinterpret_cast<const uchar2*>(g_mask + mr + nt * 8);
                if (mv.x) s_[nt][rh * 2 + 0] = -1e30f;
                if (mv.y) s_[nt][rh * 2 + 1] = -1e30f;
            }
        }

        // ---- online softmax (row = 4 lanes of a quad)
        float alpha[2];
        #pragma unroll
        for (int rh = 0; rh < 2; rh++) {
            float rmax = -1e30f;
            #pragma unroll
            for (int nt = 0; nt < 8; nt++)
                rmax = fmaxf(rmax, fmaxf(s_[nt][rh * 2], s_[nt][rh * 2 + 1]));
            rmax = fmaxf(rmax, __shfl_xor_sync(0xffffffffu, rmax, 1));
            rmax = fmaxf(rmax, __shfl_xor_sync(0xffffffffu, rmax, 2));
            const float mn = fmaxf(mI[rh], rmax);
            alpha[rh] = exp_fast(mI[rh] - mn);
            mI[rh] = mn;
            float rs = 0.f;
            #pragma unroll
            for (int nt = 0; nt < 8; nt++) {
                const float e0 = exp_fast(s_[nt][rh * 2] - mn);
                const float e1 = exp_fast(s_[nt][rh * 2 + 1] - mn);
                s_[nt][rh * 2] = e0; s_[nt][rh * 2 + 1] = e1;
                rs += e0 + e1;
            }
            rs += __shfl_xor_sync(0xffffffffu, rs, 1);
            rs += __shfl_xor_sync(0xffffffffu, rs, 2);
            lI[rh] = lI[rh] * alpha[rh] + rs;
        }
        #pragma unroll
        for (int nt = 0; nt < 8; nt++)
            #pragma unroll
            for (int e = 0; e < 4; e++) o_[nt][e] *= alpha[e >> 1];

        // ---- P @ V: 3-term split (P frags from score C-frags)
        const uint32_t sv = sk + 2 * FARRB;
        #pragma unroll
        for (int kc2 = 0; kc2 < 4; kc2++) {
            uint32_t ah[4], al[4];
            #pragma unroll
            for (int jj = 0; jj < 2; jj++) {
                const float* sp = s_[2 * kc2 + jj];
                const unsigned short h0 = f2bf(sp[0]), h1 = f2bf(sp[1]);
                const unsigned short h2 = f2bf(sp[2]), h3 = f2bf(sp[3]);
                ah[jj * 2 + 0] = (uint32_t)h0 | ((uint32_t)h1 << 16);
                ah[jj * 2 + 1] = (uint32_t)h2 | ((uint32_t)h3 << 16);
                al[jj * 2 + 0] = packbf2(sp[0] - bf2f(h0), sp[1] - bf2f(h1));
                al[jj * 2 + 1] = packbf2(sp[2] - bf2f(h2), sp[3] - bf2f(h3));
            }
            #pragma unroll
            for (int ntp = 0; ntp < 4; ntp++) {
                const uint32_t ad = sv + ((ntp * 16 + brow) * FST + kc2 * 16 + bcolh) * 2;
                uint32_t r0, r1, r2, r3;
                ldsm_x4(r0, r1, r2, r3, ad);
                { uint32_t b0[2] = {r0, r1}, b1[2] = {r2, r3};
                  mma16816(o_[2 * ntp],     ah, b0);
                  mma16816(o_[2 * ntp + 1], ah, b1);
                  mma16816(o_[2 * ntp],     al, b0);
                  mma16816(o_[2 * ntp + 1], al, b1); }
                ldsm_x4(r0, r1, r2, r3, ad + FARRB);
                { uint32_t b0[2] = {r0, r1}, b1[2] = {r2, r3};
                  mma16816(o_[2 * ntp],     ah, b0);
                  mma16816(o_[2 * ntp + 1], ah, b1); }
            }
        }
        __syncthreads();
    }

    // ---- finalize: coalesced fp32 ctx, natural head layout [B,H,S,DH]
    const float inv0 = 1.f / lI[0], inv1 = 1.f / lI[1];
    #pragma unroll
    for (int nt = 0; nt < 8; nt++) {
        const int d = nt * 8 + gc;
        const int qA = q0 + w * 16 + gr;
        *reinterpret_cast<float2*>(g_ctx + hb + (size_t)qA * DH_ + d) =
            make_float2(o_[nt][0] * inv0, o_[nt][1] * inv0);
        *reinterpret_cast<float2*>(g_ctx + hb + (size_t)(qA + 8) * DH_ + d) =
            make_float2(o_[nt][2] * inv1, o_[nt][3] * inv1);
    }
}

// ---------------------------------------------------------------------------
extern "C" void kernel_launch(void* const* d_in, const int* in_sizes, int n_in,
                              void* d_out, int out_size)
{
    const float* key   = (const float*)d_in[0];
    const float* value = (const float*)d_in[1];
    const float* query = (const float*)d_in[2];
    const void*  mask  = d_in[3];
    const float* Wq = (const float*)d_in[4];
    const float* bq = (const float*)d_in[5];
    const float* Wk = (const float*)d_in[6];
    const float* bk = (const float*)d_in[7];
    const float* Wv = (const float*)d_in[8];
    const float* bv = (const float*)d_in[9];
    const float* Wo = (const float*)d_in[10];
    const float* bo = (const float*)d_in[11];
    float* out = (float*)d_out;

    void *pctx, *pa, *pw, *pqh, *pql, *pkh, *pkl, *pvh, *pvl;
    cudaGetSymbolAddress(&pctx, g_ctx);
    cudaGetSymbolAddress(&pa,   g_abuf);
    cudaGetSymbolAddress(&pw,   g_wbuf);
    cudaGetSymbolAddress(&pqh,  g_qhi);
    cudaGetSymbolAddress(&pql,  g_qlo);
    cudaGetSymbolAddress(&pkh,  g_khi);
    cudaGetSymbolAddress(&pkl,  g_klo);
    cudaGetSymbolAddress(&pvh,  g_vhiT);
    cudaGetSymbolAddress(&pvl,  g_vloT);
    const unsigned short* abuf = (const unsigned short*)pa;
    const unsigned short* wbuf = (const unsigned short*)pw;

    // mask normalization (dtype-agnostic)
    detect_mask_kernel<<<1, 256>>>((const uint32_t*)mask);
    convert_mask_kernel<<<(MASK_N / 4 + 255) / 256, 256>>>(mask);

    const dim3 gg(D_ / 128, MTOT / 128);    // (8, 32): m = tokens
    const dim3 gv(MTOT / 128, D_ / 128);    // (32, 8): m = features (V^T)
    const int ga = (MTOT * D_ / 4) / 256;
    const int gw = (D_ * D_ / 4) / 256;

    // Q -> bf16 hi/lo natural, pre-scaled by 1/sqrt(DH)
    split_W_kernel<<<gw, 256>>>(Wq);
    split_A_kernel<<<ga, 256>>>(query, 0);
    mma_gemm_kernel<<<gg, 256>>>(abuf, wbuf, bq, nullptr,
                                 (unsigned short*)pqh, (unsigned short*)pql, 3, 0.125f);
    // K -> bf16 hi/lo natural
    split_W_kernel<<<gw, 256>>>(Wk);
    split_A_kernel<<<ga, 256>>>(key, 0);
    mma_gemm_kernel<<<gg, 256>>>(abuf, wbuf, bk, nullptr,
                                 (unsigned short*)pkh, (unsigned short*)pkl, 3, 1.f);
    // V -> bf16 hi/lo transposed [B,H,DH,S] via swapped operands (V^T = Wv X^T)
    split_W_kernel<<<gw, 256>>>(Wv);
    split_A_kernel<<<ga, 256>>>(value, 0);
    mma_gemm_kernel<<<gv, 256>>>(wbuf, abuf, bv, nullptr,
                                 (unsigned short*)pvh, (unsigned short*)pvl, 4, 1.f);

    // attention (tensorized)
    cudaFuncSetAttribute(flash_mma_kernel,
                         cudaFuncAttributeMaxDynamicSharedMemorySize, FSMEM);
    flash_mma_kernel<<<dim3(S_ / 128, H_, B_), 256, FSMEM>>>();

    // output projection
    split_W_kernel<<<gw, 256>>>(Wo);
    split_A_kernel<<<ga, 256>>>((const float*)pctx, 1);
    mma_gemm_kernel<<<gg, 256>>>(abuf, wbuf, bo, out, nullptr, nullptr, 0, 1.f);
}

// round 14
// speedup vs baseline: 1.1629x; 1.0419x over previous
#include <cuda_runtime.h>
#include <cuda_bf16.h>
#include <stdint.h>
#include <math_constants.h>

// Problem constants
#define B_   2
#define S_   2048
#define D_   1024
#define H_   16
#define DH_  64
#define MTOT (B_ * S_)          // 4096
#define MASK_N (B_ * S_ * S_)   // 8388608
#define KSPLIT 3072             // K' = 3*1024 (bf16 split folded into K)

// Scratch (device globals — allocation-free per harness rules)
__device__ int      g_mask_flags;
__device__ uint8_t  g_mask[MASK_N];
__device__ unsigned short g_abuf[MTOT * KSPLIT];  // A' bf16 [4096, 3072]
__device__ unsigned short g_wbuf[D_ * KSPLIT];    // W' bf16 [1024, 3072]
__device__ float    g_ctx[MTOT * D_];             // natural head layout [B,H,S,DH]
__device__ unsigned short g_qhi[MTOT * D_];       // [B,H,S,DH] bf16
__device__ unsigned short g_qlo[MTOT * D_];
__device__ unsigned short g_khi[MTOT * D_];
__device__ unsigned short g_klo[MTOT * D_];
__device__ unsigned short g_vhiT[MTOT * D_];      // [B,H,DH,S] bf16
__device__ unsigned short g_vloT[MTOT * D_];

// ---------------------------------------------------------------------------
// helpers
// ---------------------------------------------------------------------------
__device__ __forceinline__ uint32_t smem_u32(const void* p) {
    uint32_t a;
    asm("{ .reg .u64 t; cvta.to.shared.u64 t, %1; cvt.u32.u64 %0, t; }"
        : "=r"(a) : "l"(p));
    return a;
}
__device__ __forceinline__ void ldsm_x4(uint32_t& r0, uint32_t& r1,
                                        uint32_t& r2, uint32_t& r3, uint32_t addr) {
    asm volatile("ldmatrix.sync.aligned.m8n8.x4.shared.b16 {%0,%1,%2,%3}, [%4];"
                 : "=r"(r0), "=r"(r1), "=r"(r2), "=r"(r3) : "r"(addr));
}
__device__ __forceinline__ void ldsm_x2(uint32_t& r0, uint32_t& r1, uint32_t addr) {
    asm volatile("ldmatrix.sync.aligned.m8n8.x2.shared.b16 {%0,%1}, [%2];"
                 : "=r"(r0), "=r"(r1) : "r"(addr));
}
__device__ __forceinline__ void mma16816(float* c, const uint32_t* a, const uint32_t* b) {
    asm volatile(
        "mma.sync.aligned.m16n8k16.row.col.f32.bf16.bf16.f32 "
        "{%0,%1,%2,%3}, {%4,%5,%6,%7}, {%8,%9}, {%0,%1,%2,%3};"
        : "+f"(c[0]), "+f"(c[1]), "+f"(c[2]), "+f"(c[3])
        : "r"(a[0]), "r"(a[1]), "r"(a[2]), "r"(a[3]), "r"(b[0]), "r"(b[1]));
}
__device__ __forceinline__ void cpa16(uint32_t saddr, const void* g) {
    asm volatile("cp.async.ca.shared.global [%0], [%1], 16;" :: "r"(saddr), "l"(g));
}
__device__ __forceinline__ unsigned short f2bf(float x) {
    return __bfloat16_as_ushort(__float2bfloat16_rn(x));
}
__device__ __forceinline__ float bf2f(unsigned short u) {
    return __bfloat162float(__ushort_as_bfloat16(u));
}
__device__ __forceinline__ uint32_t packbf2(float a, float b) {
    return (uint32_t)f2bf(a) | ((uint32_t)f2bf(b) << 16);
}
// MUFU-free exp: magic round + deg-5 exp2 poly + exponent add. x <= 0 expected.
__device__ __forceinline__ float exp_fast(float x) {
    float y = fmaxf(x * 1.4426950408889634f, -126.0f);
    const float t  = y + 12582912.0f;
    const float nf = t - 12582912.0f;
    const float f  = y - nf;
    float p = 0.0013339075f;
    p = fmaf(p, f, 0.0096181691f);
    p = fmaf(p, f, 0.0555041086f);
    p = fmaf(p, f, 0.2402265069f);
    p = fmaf(p, f, 0.6931471806f);
    p = fmaf(p, f, 1.0f);
    return __int_as_float(__float_as_int(p) + (((int)nf) << 23));
}

// ---------------------------------------------------------------------------
// Mask dtype detection + normalization (R2-verified, R6 form)
// ---------------------------------------------------------------------------
__global__ __launch_bounds__(256) void detect_mask_kernel(const uint32_t* __restrict__ raw)
{
    __shared__ int sflags[256];
    int f = 0;
    const int tid = threadIdx.x;
    #pragma unroll
    for (int i = 0; i < 16; i++) {
        const uint32_t w = raw[tid * 16 + i];
        if (w != 0u && w != 1u)          f |= 1;
        if (w != 0u && w != 0x3F800000u) f |= 2;
    }
    sflags[tid] = f;
    __syncthreads();
    for (int s = 128; s > 0; s >>= 1) {
        if (tid < s) sflags[tid] |= sflags[tid + s];
        __syncthreads();
    }
    if (tid == 0) g_mask_flags = sflags[0];
}

__global__ __launch_bounds__(256) void convert_mask_kernel(const void* __restrict__ raw)
{
    const int flags = g_mask_flags;
    const size_t i0 = ((size_t)blockIdx.x * 256 + threadIdx.x) * 4;
    if (i0 >= MASK_N) return;
    uchar4 o;
    if ((flags & 1) == 0) {
        const int4 v = *reinterpret_cast<const int4*>((const int*)raw + i0);
        o = make_uchar4(v.x != 0, v.y != 0, v.z != 0, v.w != 0);
    } else if ((flags & 2) == 0) {
        const float4 v = *reinterpret_cast<const float4*>((const float*)raw + i0);
        o = make_uchar4(v.x != 0.f, v.y != 0.f, v.z != 0.f, v.w != 0.f);
    } else {
        o = *reinterpret_cast<const uchar4*>((const uint8_t*)raw + i0);
        o = make_uchar4(o.x != 0, o.y != 0, o.z != 0, o.w != 0);
    }
    *reinterpret_cast<uchar4*>(g_mask + i0) = o;
}

// ---------------------------------------------------------------------------
// Split-bf16 conversion:  A' = [hi|hi|lo],  W' = [hi|lo|hi]   (K'=3072)
// ---------------------------------------------------------------------------
__global__ __launch_bounds__(256) void split_A_kernel(const float* __restrict__ A, int gather)
{
    const int t  = blockIdx.x * 256 + threadIdx.x;
    const int e0 = t * 4;
    const int m  = e0 >> 10, k = e0 & 1023;
    float4 v;
    if (!gather) {
        v = *reinterpret_cast<const float4*>(A + (size_t)m * D_ + k);
    } else {
        const int b = m >> 11, s = m & (S_ - 1);
        const int h = k >> 6, dh = k & 63;
        v = *reinterpret_cast<const float4*>(
            A + ((((size_t)b * H_ + h) * S_ + s) << 6) + dh);
    }
    ushort4 hi = make_ushort4(f2bf(v.x), f2bf(v.y), f2bf(v.z), f2bf(v.w));
    ushort4 lo = make_ushort4(f2bf(v.x - bf2f(hi.x)), f2bf(v.y - bf2f(hi.y)),
                              f2bf(v.z - bf2f(hi.z)), f2bf(v.w - bf2f(hi.w)));
    const size_t base = (size_t)m * KSPLIT;
    *reinterpret_cast<ushort4*>(g_abuf + base + k)        = hi;
    *reinterpret_cast<ushort4*>(g_abuf + base + 1024 + k) = hi;
    *reinterpret_cast<ushort4*>(g_abuf + base + 2048 + k) = lo;
}

__global__ __launch_bounds__(256) void split_W_kernel(const float* __restrict__ W)
{
    const int t  = blockIdx.x * 256 + threadIdx.x;
    const int e0 = t * 4;
    const int n  = e0 >> 10, k = e0 & 1023;
    const float4 v = *reinterpret_cast<const float4*>(W + (size_t)n * D_ + k);
    ushort4 hi = make_ushort4(f2bf(v.x), f2bf(v.y), f2bf(v.z), f2bf(v.w));
    ushort4 lo = make_ushort4(f2bf(v.x - bf2f(hi.x)), f2bf(v.y - bf2f(hi.y)),
                              f2bf(v.z - bf2f(hi.z)), f2bf(v.w - bf2f(hi.w)));
    const size_t base = (size_t)n * KSPLIT;
    *reinterpret_cast<ushort4*>(g_wbuf + base + k)        = hi;
    *reinterpret_cast<ushort4*>(g_wbuf + base + 1024 + k) = lo;
    *reinterpret_cast<ushort4*>(g_wbuf + base + 2048 + k) = hi;
}

// ---------------------------------------------------------------------------
// HMMA GEMM: C[m][n] = sum_k A'[m][k]*W'[n][k] (+bias)*scale
// CTA 128x128, 8 warps (2m x 4n), warp tile 64x32, BK=32, double-buffered.
// __launch_bounds__(256, 2): 2 CTAs/SM (verified win in R12).
//   omode 0: fp32 out[m][D_ cols]   (bias[n])
//   omode 3: bf16 hi/lo -> natural [B,H,S,DH]; m=token, n=feature (bias[n])
//   omode 4: bf16 hi/lo -> V^T [B,H,DH,S];    m=feature, n=token  (bias[m])
// ---------------------------------------------------------------------------
#define BK    32
#define SST   40
#define SMATE (128 * SST)
#define STAGE (2 * SMATE)
#define NCHUNK (KSPLIT / BK)         // 96

__global__ __launch_bounds__(256, 2) void mma_gemm_kernel(
    const unsigned short* __restrict__ Abuf, const unsigned short* __restrict__ Wbuf,
    const float* __restrict__ bias, float* __restrict__ out,
    unsigned short* __restrict__ ohi, unsigned short* __restrict__ olo,
    int omode, float scale)
{
    __shared__ __align__(16) unsigned short sbuf[2 * STAGE];  // 40960 B

    const int tid  = threadIdx.x;
    const int wid  = tid >> 5, lane = tid & 31;
    const int wm   = wid >> 2, wn = wid & 3;
    const int m0   = blockIdx.y * 128, n0 = blockIdx.x * 128;

    const uint32_t sb = smem_u32(sbuf);

    float acc[4][4][4];
    #pragma unroll
    for (int i = 0; i < 4; i++)
        #pragma unroll
        for (int j = 0; j < 4; j++)
            #pragma unroll
            for (int e = 0; e < 4; e++) acc[i][j][e] = 0.f;

    const int lrow0 = tid >> 2, lseg = (tid & 3) * 8;

    {
        const unsigned short* Ap = Abuf + (size_t)(m0 + lrow0) * KSPLIT + lseg;
        const unsigned short* Bp = Wbuf + (size_t)(n0 + lrow0) * KSPLIT + lseg;
        *reinterpret_cast<uint4*>(sbuf + lrow0 * SST + lseg) =
            *reinterpret_cast<const uint4*>(Ap);
        *reinterpret_cast<uint4*>(sbuf + (lrow0 + 64) * SST + lseg) =
            *reinterpret_cast<const uint4*>(Ap + (size_t)64 * KSPLIT);
        *reinterpret_cast<uint4*>(sbuf + SMATE + lrow0 * SST + lseg) =
            *reinterpret_cast<const uint4*>(Bp);
        *reinterpret_cast<uint4*>(sbuf + SMATE + (lrow0 + 64) * SST + lseg) =
            *reinterpret_cast<const uint4*>(Bp + (size_t)64 * KSPLIT);
    }
    __syncthreads();

    const int a_row  = wm * 64 + (lane & 15);
    const int a_colh = (lane >> 4) * 8;
    const int b_row  = wn * 32 + (lane & 7);
    const int b_colh = ((lane >> 3) & 1) * 8;

    for (int c = 0; c < NCHUNK; c++) {
        const int st = c & 1;
        const uint32_t sa  = sb + (uint32_t)(st * STAGE) * 2;
        const uint32_t sbm = sa + (uint32_t)SMATE * 2;

        uint4 pa0, pa1, pb0, pb1;
        if (c + 1 < NCHUNK) {
            const int k0 = (c + 1) * BK;
            const unsigned short* Ap = Abuf + (size_t)(m0 + lrow0) * KSPLIT + k0 + lseg;
            const unsigned short* Bp = Wbuf + (size_t)(n0 + lrow0) * KSPLIT + k0 + lseg;
            pa0 = *reinterpret_cast<const uint4*>(Ap);
            pa1 = *reinterpret_cast<const uint4*>(Ap + (size_t)64 * KSPLIT);
            pb0 = *reinterpret_cast<const uint4*>(Bp);
            pb1 = *reinterpret_cast<const uint4*>(Bp + (size_t)64 * KSPLIT);
        }

        #pragma unroll
        for (int ks = 0; ks < 2; ks++) {
            uint32_t a[4][4], b[4][2];
            #pragma unroll
            for (int mt = 0; mt < 4; mt++) {
                const uint32_t addr = sa +
                    ((a_row + mt * 16) * SST + ks * 16 + a_colh) * 2;
                ldsm_x4(a[mt][0], a[mt][1], a[mt][2], a[mt][3], addr);
            }
            #pragma unroll
            for (int nt = 0; nt < 4; nt++) {
                const uint32_t addr = sbm +
                    ((b_row + nt * 8) * SST + ks * 16 + b_colh) * 2;
                ldsm_x2(b[nt][0], b[nt][1], addr);
            }
            #pragma unroll
            for (int mt = 0; mt < 4; mt++)
                #pragma unroll
                for (int nt = 0; nt < 4; nt++)
                    mma16816(acc[mt][nt], a[mt], b[nt]);
        }

        if (c + 1 < NCHUNK) {
            unsigned short* d = sbuf + (st ^ 1) * STAGE;
            *reinterpret_cast<uint4*>(d + lrow0 * SST + lseg) = pa0;
            *reinterpret_cast<uint4*>(d + (lrow0 + 64) * SST + lseg) = pa1;
            *reinterpret_cast<uint4*>(d + SMATE + lrow0 * SST + lseg) = pb0;
            *reinterpret_cast<uint4*>(d + SMATE + (lrow0 + 64) * SST + lseg) = pb1;
        }
        __syncthreads();
    }

    const int gr = lane >> 2, gc = (lane & 3) * 2;
    #pragma unroll
    for (int mt = 0; mt < 4; mt++) {
        #pragma unroll
        for (int nt = 0; nt < 4; nt++) {
            const int n = n0 + wn * 32 + nt * 8 + gc;
            #pragma unroll
            for (int half = 0; half < 2; half++) {
                const int m = m0 + wm * 64 + mt * 16 + gr + half * 8;
                float bb0, bb1;
                if (omode == 4) { bb0 = bb1 = bias[m]; }
                else           { bb0 = bias[n]; bb1 = bias[n + 1]; }
                const float v0 = (acc[mt][nt][half * 2 + 0] + bb0) * scale;
                const float v1 = (acc[mt][nt][half * 2 + 1] + bb1) * scale;
                if (omode == 0) {
                    *reinterpret_cast<float2*>(out + (size_t)m * D_ + n) =
                        make_float2(v0, v1);
                } else if (omode == 3) {
                    const int bb = m >> 11, s = m & (S_ - 1);
                    const int hh = n >> 6, dh = n & 63;
                    const size_t ad = (((size_t)bb * H_ + hh) * S_ + s) * DH_ + dh;
                    const ushort2 sh = make_ushort2(f2bf(v0), f2bf(v1));
                    const ushort2 sl = make_ushort2(f2bf(v0 - bf2f(sh.x)),
                                                    f2bf(v1 - bf2f(sh.y)));
                    *reinterpret_cast<ushort2*>(ohi + ad) = sh;
                    *reinterpret_cast<ushort2*>(olo + ad) = sl;
                } else {  // omode 4: V^T
                    const int hh = m >> 6, dh = m & 63;
                    const int bb = n >> 11, s = n & (S_ - 1);
                    const size_t ad = (((size_t)bb * H_ + hh) * DH_ + dh) * S_ + s;
                    const ushort2 sh = make_ushort2(f2bf(v0), f2bf(v1));
                    const ushort2 sl = make_ushort2(f2bf(v0 - bf2f(sh.x)),
                                                    f2bf(v1 - bf2f(sh.y)));
                    *reinterpret_cast<ushort2*>(ohi + ad) = sh;
                    *reinterpret_cast<ushort2*>(olo + ad) = sl;
                }
            }
        }
    }
}

// ---------------------------------------------------------------------------
// Tensorized flash attention (R12 structure; R13 change: 2 CTAs/SM).
// Q frags in registers, cp.async double-buffer, uchar mask, fp32 coalesced ctx.
// smem 73.7 KB/CTA -> 2 CTAs = 147.5 KB, fits the 228 KB carveout.
// ---------------------------------------------------------------------------
#define FST   72                     // smem row stride (ushort), conflict-free
#define FARRB (64 * FST * 2)         // bytes per 64-row array = 9216
#define FSTGB (4 * FARRB)            // per stage = 36864 B
#define FSMEM (2 * FSTGB)            // 73728 B

__global__ __launch_bounds__(256, 2) void flash_mma_kernel()
{
    extern __shared__ __align__(16) unsigned char fsm[];
    const int tid = threadIdx.x, w = tid >> 5, lane = tid & 31;
    const int q0 = blockIdx.x * 128;
    const int h  = blockIdx.y, b = blockIdx.z;
    const size_t hb = ((size_t)b * H_ + h) * (size_t)(S_ * DH_);
    const uint32_t sb = smem_u32(fsm);

    // ---- Q staged through smem (hi at 0, lo at FSTGB), frags -> registers
    #pragma unroll
    for (int i = 0; i < 4; i++) {
        const int f = tid + i * 256;
        const int r = f >> 3, sg = f & 7;
        const size_t gq = hb + (size_t)(q0 + r) * DH_ + sg * 8;
        *reinterpret_cast<uint4*>(fsm + (r * FST + sg * 8) * 2) =
            *reinterpret_cast<const uint4*>(g_qhi + gq);
        *reinterpret_cast<uint4*>(fsm + FSTGB + (r * FST + sg * 8) * 2) =
            *reinterpret_cast<const uint4*>(g_qlo + gq);
    }
    __syncthreads();
    uint32_t qh[4][4], ql[4][4];
    {
        const int ar = w * 16 + (lane & 15);
        const int ac = (lane >> 4) * 8;
        #pragma unroll
        for (int kc = 0; kc < 4; kc++) {
            const uint32_t ad = sb + (ar * FST + kc * 16 + ac) * 2;
            ldsm_x4(qh[kc][0], qh[kc][1], qh[kc][2], qh[kc][3], ad);
            ldsm_x4(ql[kc][0], ql[kc][1], ql[kc][2], ql[kc][3], ad + FSTGB);
        }
    }
    __syncthreads();

    const int gr = lane >> 2, gc = (lane & 3) * 2;
    const int brow  = (lane & 7) + ((lane >> 4) & 1) * 8;
    const int bcolh = ((lane >> 3) & 1) * 8;

    float o_[8][4];
    #pragma unroll
    for (int nt = 0; nt < 8; nt++)
        #pragma unroll
        for (int e = 0; e < 4; e++) o_[nt][e] = 0.f;
    float mI[2] = {-1e30f, -1e30f}, lI[2] = {0.f, 0.f};

    auto issue_kv = [&](int kt, int st) {
        const uint32_t s0 = sb + st * FSTGB;
        const int k0 = kt * 64;
        #pragma unroll
        for (int i = 0; i < 2; i++) {
            const int f = tid + i * 256;
            const int r = f >> 3, sg = f & 7;
            const uint32_t so = (r * FST + sg * 8) * 2;
            const size_t kg = hb + (size_t)(k0 + r) * DH_ + sg * 8;
            cpa16(s0 + so,             g_khi + kg);
            cpa16(s0 + FARRB + so,     g_klo + kg);
            const size_t vg = hb + (size_t)r * S_ + k0 + sg * 8;
            cpa16(s0 + 2 * FARRB + so, g_vhiT + vg);
            cpa16(s0 + 3 * FARRB + so, g_vloT + vg);
        }
    };

    issue_kv(0, 0);
    asm volatile("cp.async.commit_group;" ::: "memory");

    for (int kt = 0; kt < S_ / 64; kt++) {
        const int st = kt & 1;
        if (kt + 1 < S_ / 64) {
            issue_kv(kt + 1, st ^ 1);
            asm volatile("cp.async.commit_group;" ::: "memory");
            asm volatile("cp.async.wait_group 1;" ::: "memory");
        } else {
            asm volatile("cp.async.wait_group 0;" ::: "memory");
        }
        __syncthreads();

        const uint32_t sk = sb + st * FSTGB;

        // ---- QK^T: 3-term split
        float s_[8][4];
        #pragma unroll
        for (int nt = 0; nt < 8; nt++)
            #pragma unroll
            for (int e = 0; e < 4; e++) s_[nt][e] = 0.f;

        #pragma unroll
        for (int kc = 0; kc < 4; kc++) {
            #pragma unroll
            for (int ntp = 0; ntp < 4; ntp++) {
                const uint32_t ad = sk + ((ntp * 16 + brow) * FST + kc * 16 + bcolh) * 2;
                uint32_t r0, r1, r2, r3;
                ldsm_x4(r0, r1, r2, r3, ad);
                { uint32_t b0[2] = {r0, r1}, b1[2] = {r2, r3};
                  mma16816(s_[2 * ntp],     qh[kc], b0);
                  mma16816(s_[2 * ntp + 1], qh[kc], b1);
                  mma16816(s_[2 * ntp],     ql[kc], b0);
                  mma16816(s_[2 * ntp + 1], ql[kc], b1); }
                ldsm_x4(r0, r1, r2, r3, ad + FARRB);
                { uint32_t b0[2] = {r0, r1}, b1[2] = {r2, r3};
                  mma16816(s_[2 * ntp],     qh[kc], b0);
                  mma16816(s_[2 * ntp + 1], qh[kc], b1); }
            }
        }

        // ---- mask (canonical uint8)
        const int k0 = kt * 64;
        #pragma unroll
        for (int rh = 0; rh < 2; rh++) {
            const size_t mr = ((size_t)b * S_ + (q0 + w * 16 + gr + rh * 8)) * S_ + k0 + gc;
            #pragma unroll
            for (int nt = 0; nt < 8; nt++) {
                const uchar2 mv = *reinterpret_cast<const uchar2*>(g_mask + mr + nt * 8);
                if (mv.x) s_[nt][rh * 2 + 0] = -1e30f;
                if (mv.y) s_[nt][rh * 2 + 1] = -1e30f;
            }
        }

        // ---- online softmax (row = 4 lanes of a quad)
        float alpha[2];
        #pragma unroll
        for (int rh = 0; rh < 2; rh++) {
            float rmax = -1e30f;
            #pragma unroll
            for (int nt = 0; nt < 8; nt++)
                rmax = fmaxf(rmax, fmaxf(s_[nt][rh * 2], s_[nt][rh * 2 + 1]));
            rmax = fmaxf(rmax, __shfl_xor_sync(0xffffffffu, rmax, 1));
            rmax = fmaxf(rmax, __shfl_xor_sync(0xffffffffu, rmax, 2));
            const float mn = fmaxf(mI[rh], rmax);
            alpha[rh] = exp_fast(mI[rh] - mn);
            mI[rh] = mn;
            float rs = 0.f;
            #pragma unroll
            for (int nt = 0; nt < 8; nt++) {
                const float e0 = exp_fast(s_[nt][rh * 2] - mn);
                const float e1 = exp_fast(s_[nt][rh * 2 + 1] - mn);
                s_[nt][rh * 2] = e0; s_[nt][rh * 2 + 1] = e1;
                rs += e0 + e1;
            }
            rs += __shfl_xor_sync(0xffffffffu, rs, 1);
            rs += __shfl_xor_sync(0xffffffffu, rs, 2);
            lI[rh] = lI[rh] * alpha[rh] + rs;
        }
        #pragma unroll
        for (int nt = 0; nt < 8; nt++)
            #pragma unroll
            for (int e = 0; e < 4; e++) o_[nt][e] *= alpha[e >> 1];

        // ---- P @ V: 3-term split (P frags from score C-frags)
        const uint32_t sv = sk + 2 * FARRB;
        #pragma unroll
        for (int kc2 = 0; kc2 < 4; kc2++) {
            uint32_t ah[4], al[4];
            #pragma unroll
            for (int jj = 0; jj < 2; jj++) {
                const float* sp = s_[2 * kc2 + jj];
                const unsigned short h0 = f2bf(sp[0]), h1 = f2bf(sp[1]);
                const unsigned short h2 = f2bf(sp[2]), h3 = f2bf(sp[3]);
                ah[jj * 2 + 0] = (uint32_t)h0 | ((uint32_t)h1 << 16);
                ah[jj * 2 + 1] = (uint32_t)h2 | ((uint32_t)h3 << 16);
                al[jj * 2 + 0] = packbf2(sp[0] - bf2f(h0), sp[1] - bf2f(h1));
                al[jj * 2 + 1] = packbf2(sp[2] - bf2f(h2), sp[3] - bf2f(h3));
            }
            #pragma unroll
            for (int ntp = 0; ntp < 4; ntp++) {
                const uint32_t ad = sv + ((ntp * 16 + brow) * FST + kc2 * 16 + bcolh) * 2;
                uint32_t r0, r1, r2, r3;
                ldsm_x4(r0, r1, r2, r3, ad);
                { uint32_t b0[2] = {r0, r1}, b1[2] = {r2, r3};
                  mma16816(o_[2 * ntp],     ah, b0);
                  mma16816(o_[2 * ntp + 1], ah, b1);
                  mma16816(o_[2 * ntp],     al, b0);
                  mma16816(o_[2 * ntp + 1], al, b1); }
                ldsm_x4(r0, r1, r2, r3, ad + FARRB);
                { uint32_t b0[2] = {r0, r1}, b1[2] = {r2, r3};
                  mma16816(o_[2 * ntp],     ah, b0);
                  mma16816(o_[2 * ntp + 1], ah, b1); }
            }
        }
        __syncthreads();
    }

    // ---- finalize: coalesced fp32 ctx, natural head layout [B,H,S,DH]
    const float inv0 = 1.f / lI[0], inv1 = 1.f / lI[1];
    #pragma unroll
    for (int nt = 0; nt < 8; nt++) {
        const int d = nt * 8 + gc;
        const int qA = q0 + w * 16 + gr;
        *reinterpret_cast<float2*>(g_ctx + hb + (size_t)qA * DH_ + d) =
            make_float2(o_[nt][0] * inv0, o_[nt][1] * inv0);
        *reinterpret_cast<float2*>(g_ctx + hb + (size_t)(qA + 8) * DH_ + d) =
            make_float2(o_[nt][2] * inv1, o_[nt][3] * inv1);
    }
}

// ---------------------------------------------------------------------------
extern "C" void kernel_launch(void* const* d_in, const int* in_sizes, int n_in,
                              void* d_out, int out_size)
{
    const float* key   = (const float*)d_in[0];
    const float* value = (const float*)d_in[1];
    const float* query = (const float*)d_in[2];
    const void*  mask  = d_in[3];
    const float* Wq = (const float*)d_in[4];
    const float* bq = (const float*)d_in[5];
    const float* Wk = (const float*)d_in[6];
    const float* bk = (const float*)d_in[7];
    const float* Wv = (const float*)d_in[8];
    const float* bv = (const float*)d_in[9];
    const float* Wo = (const float*)d_in[10];
    const float* bo = (const float*)d_in[11];
    float* out = (float*)d_out;

    void *pctx, *pa, *pw, *pqh, *pql, *pkh, *pkl, *pvh, *pvl;
    cudaGetSymbolAddress(&pctx, g_ctx);
    cudaGetSymbolAddress(&pa,   g_abuf);
    cudaGetSymbolAddress(&pw,   g_wbuf);
    cudaGetSymbolAddress(&pqh,  g_qhi);
    cudaGetSymbolAddress(&pql,  g_qlo);
    cudaGetSymbolAddress(&pkh,  g_khi);
    cudaGetSymbolAddress(&pkl,  g_klo);
    cudaGetSymbolAddress(&pvh,  g_vhiT);
    cudaGetSymbolAddress(&pvl,  g_vloT);
    const unsigned short* abuf = (const unsigned short*)pa;
    const unsigned short* wbuf = (const unsigned short*)pw;

    // mask normalization (dtype-agnostic)
    detect_mask_kernel<<<1, 256>>>((const uint32_t*)mask);
    convert_mask_kernel<<<(MASK_N / 4 + 255) / 256, 256>>>(mask);

    const dim3 gg(D_ / 128, MTOT / 128);    // (8, 32): m = tokens
    const dim3 gv(MTOT / 128, D_ / 128);    // (32, 8): m = features (V^T)
    const int ga = (MTOT * D_ / 4) / 256;
    const int gw = (D_ * D_ / 4) / 256;

    // Q -> bf16 hi/lo natural, pre-scaled by 1/sqrt(DH)
    split_W_kernel<<<gw, 256>>>(Wq);
    split_A_kernel<<<ga, 256>>>(query, 0);
    mma_gemm_kernel<<<gg, 256>>>(abuf, wbuf, bq, nullptr,
                                 (unsigned short*)pqh, (unsigned short*)pql, 3, 0.125f);
    // K -> bf16 hi/lo natural
    split_W_kernel<<<gw, 256>>>(Wk);
    split_A_kernel<<<ga, 256>>>(key, 0);
    mma_gemm_kernel<<<gg, 256>>>(abuf, wbuf, bk, nullptr,
                                 (unsigned short*)pkh, (unsigned short*)pkl, 3, 1.f);
    // V -> bf16 hi/lo transposed [B,H,DH,S] via swapped operands (V^T = Wv X^T)
    split_W_kernel<<<gw, 256>>>(Wv);
    split_A_kernel<<<ga, 256>>>(value, 0);
    mma_gemm_kernel<<<gv, 256>>>(wbuf, abuf, bv, nullptr,
                                 (unsigned short*)pvh, (unsigned short*)pvl, 4, 1.f);

    // attention (tensorized, 2 CTAs/SM)
    cudaFuncSetAttribute(flash_mma_kernel,
                         cudaFuncAttributeMaxDynamicSharedMemorySize, FSMEM);
    flash_mma_kernel<<<dim3(S_ / 128, H_, B_), 256, FSMEM>>>();

    // output projection
    split_W_kernel<<<gw, 256>>>(Wo);
    split_A_kernel<<<ga, 256>>>((const float*)pctx, 1);
    mma_gemm_kernel<<<gg, 256>>>(abuf, wbuf, bo, out, nullptr, nullptr, 0, 1.f);
}